// round 1
// baseline (speedup 1.0000x reference)
#include <cuda_runtime.h>
#include <math.h>

// ---------------------------------------------------------------------------
// GatedDeltaNetVarlen: fp32 baseline
//   1) mixed = hs @ W_qkv^T      (1536 x 2048)
//   2) z     = hs @ W_z^T        (1536 x 1024)
//   3) b,a -> beta, g            (1536 x 16 each)
//   4) causal depthwise conv(4) + silu -> qkv buffer
//   5) per-head L2 norm of q (x DK^-0.5) and k
//   6) sequential gated delta rule per (seq, head)   -> o
//   7) gated RMSNorm (gate = silu(z))                -> on
//   8) out = on @ W_out^T        (1536 x 1024)  -> d_out
// ---------------------------------------------------------------------------

#define TOTAL_MAX 1536
#define HIDDEN    1024
#define CONV_DIM  2048
#define KEY_DIM   512
#define VAL_DIM   1024
#define HK        8
#define HV        16
#define DK        64
#define DV        64
#define KSZ       4

__device__ float g_mixed[TOTAL_MAX * CONV_DIM];
__device__ float g_qkv  [TOTAL_MAX * CONV_DIM];
__device__ float g_z    [TOTAL_MAX * VAL_DIM];
__device__ float g_beta [TOTAL_MAX * HV];
__device__ float g_gate [TOTAL_MAX * HV];
__device__ float g_o    [TOTAL_MAX * VAL_DIM];
__device__ float g_on   [TOTAL_MAX * VAL_DIM];

// ---------------------------------------------------------------------------
// Tiled SGEMM:  C[M,N] = A[M,K] @ W[N,K]^T   (A, W, C row-major)
// BM=BN=128, BK=16, 256 threads, 8x8 per thread.
// Requires M%128==0, N%128==0, K%16==0 (true for this problem).
// ---------------------------------------------------------------------------
#define BM 128
#define BN 128
#define BKK 16

__global__ __launch_bounds__(256) void sgemm_tn(
    const float* __restrict__ A, const float* __restrict__ W,
    float* __restrict__ C, int M, int N, int K)
{
    __shared__ float As[BKK][BM];
    __shared__ float Ws[BKK][BN];

    const int tid = threadIdx.x;
    const int bm = blockIdx.y * BM;
    const int bn = blockIdx.x * BN;
    const int tx = tid & 15;      // 0..15 : column group
    const int ty = tid >> 4;      // 0..15 : row group

    const int lr = tid >> 2;         // 0..63
    const int lc = (tid & 3) << 2;   // 0,4,8,12

    float acc[8][8];
#pragma unroll
    for (int i = 0; i < 8; i++)
#pragma unroll
        for (int j = 0; j < 8; j++) acc[i][j] = 0.f;

    for (int k0 = 0; k0 < K; k0 += BKK) {
#pragma unroll
        for (int half = 0; half < 2; half++) {
            int r = lr + half * 64;
            float4 av = *(const float4*)(A + (size_t)(bm + r) * K + k0 + lc);
            As[lc + 0][r] = av.x; As[lc + 1][r] = av.y;
            As[lc + 2][r] = av.z; As[lc + 3][r] = av.w;
            float4 wv = *(const float4*)(W + (size_t)(bn + r) * K + k0 + lc);
            Ws[lc + 0][r] = wv.x; Ws[lc + 1][r] = wv.y;
            Ws[lc + 2][r] = wv.z; Ws[lc + 3][r] = wv.w;
        }
        __syncthreads();

#pragma unroll
        for (int kk = 0; kk < BKK; kk++) {
            float af[8], wf[8];
#pragma unroll
            for (int i = 0; i < 8; i++) af[i] = As[kk][ty * 8 + i];
#pragma unroll
            for (int j = 0; j < 8; j++) wf[j] = Ws[kk][tx * 8 + j];
#pragma unroll
            for (int i = 0; i < 8; i++)
#pragma unroll
                for (int j = 0; j < 8; j++)
                    acc[i][j] = fmaf(af[i], wf[j], acc[i][j]);
        }
        __syncthreads();
    }

#pragma unroll
    for (int i = 0; i < 8; i++) {
        size_t r = (size_t)(bm + ty * 8 + i);
#pragma unroll
        for (int j = 0; j < 8; j += 4) {
            float4 cv = make_float4(acc[i][j], acc[i][j + 1], acc[i][j + 2], acc[i][j + 3]);
            *(float4*)(C + r * N + bn + tx * 8 + j) = cv;
        }
    }
}

// ---------------------------------------------------------------------------
// b,a projections (N=16 each) fused with beta = sigmoid(b),
// g = -exp(A_log) * softplus(a + dt_bias).  One block per token, 8 warps,
// each warp produces 4 of the 32 outputs.
// ---------------------------------------------------------------------------
__global__ __launch_bounds__(256) void ba_kernel(
    const float* __restrict__ hs,
    const float* __restrict__ Wb, const float* __restrict__ Wa,
    const float* __restrict__ dtb, const float* __restrict__ Alog,
    float* __restrict__ beta, float* __restrict__ gate)
{
    const int t = blockIdx.x;
    const int w = threadIdx.x >> 5;
    const int lane = threadIdx.x & 31;
    const int obase = w * 4;

    const float* __restrict__ x = hs + (size_t)t * HIDDEN;
    const float* Wp[4];
#pragma unroll
    for (int r = 0; r < 4; r++) {
        int o = obase + r;
        Wp[r] = (o < HV) ? (Wb + (size_t)o * HIDDEN) : (Wa + (size_t)(o - HV) * HIDDEN);
    }

    float acc[4] = {0.f, 0.f, 0.f, 0.f};
#pragma unroll 4
    for (int i = 0; i < HIDDEN / 32; i++) {
        float xv = x[i * 32 + lane];
#pragma unroll
        for (int r = 0; r < 4; r++)
            acc[r] = fmaf(xv, Wp[r][i * 32 + lane], acc[r]);
    }
#pragma unroll
    for (int r = 0; r < 4; r++)
#pragma unroll
        for (int off = 16; off; off >>= 1)
            acc[r] += __shfl_xor_sync(0xffffffffu, acc[r], off);

    if (lane == 0) {
#pragma unroll
        for (int r = 0; r < 4; r++) {
            int o = obase + r;
            if (o < HV) {
                beta[(size_t)t * HV + o] = 1.f / (1.f + expf(-acc[r]));
            } else {
                int h = o - HV;
                float xv = acc[r] + dtb[h];
                float sp = (xv > 20.f) ? xv : log1pf(expf(xv));
                gate[(size_t)t * HV + h] = -expf(Alog[h]) * sp;
            }
        }
    }
}

// ---------------------------------------------------------------------------
// Causal depthwise conv (ksz=4, per-sequence) + silu
// ---------------------------------------------------------------------------
__global__ __launch_bounds__(256) void conv_silu_kernel(
    const float* __restrict__ mixed, const float* __restrict__ cw,
    const int* __restrict__ cu, int B, float* __restrict__ out)
{
    const int t = blockIdx.x;
    const int c = blockIdx.y * blockDim.x + threadIdx.x;

    int start = 0;
    for (int i = 1; i < B; i++) { int s = cu[i]; if (t >= s) start = s; }

    const float w0 = cw[c * 4 + 0], w1 = cw[c * 4 + 1];
    const float w2 = cw[c * 4 + 2], w3 = cw[c * 4 + 3];

    float y = mixed[(size_t)t * CONV_DIM + c] * w3;
    if (t - 1 >= start) y = fmaf(mixed[(size_t)(t - 1) * CONV_DIM + c], w2, y);
    if (t - 2 >= start) y = fmaf(mixed[(size_t)(t - 2) * CONV_DIM + c], w1, y);
    if (t - 3 >= start) y = fmaf(mixed[(size_t)(t - 3) * CONV_DIM + c], w0, y);

    y = y / (1.f + expf(-y));  // silu
    out[(size_t)t * CONV_DIM + c] = y;
}

// ---------------------------------------------------------------------------
// Per-head L2 norm of q (heads 0..7, channels [0,512)) and k ([512,1024)).
// q additionally scaled by DK^-0.5 = 0.125.  16 warps per token.
// ---------------------------------------------------------------------------
__global__ __launch_bounds__(512) void qknorm_kernel(float* __restrict__ qkv)
{
    const int t = blockIdx.x;
    const int w = threadIdx.x >> 5;
    const int lane = threadIdx.x & 31;
    const size_t base = (size_t)t * CONV_DIM + w * 64;  // w<8: q head w ; w>=8: k head w-8

    float x0 = qkv[base + lane];
    float x1 = qkv[base + 32 + lane];
    float ss = x0 * x0 + x1 * x1;
#pragma unroll
    for (int off = 16; off; off >>= 1)
        ss += __shfl_xor_sync(0xffffffffu, ss, off);
    float r = rsqrtf(ss + 1e-6f);
    if (w < 8) r *= 0.125f;
    qkv[base + lane]      = x0 * r;
    qkv[base + 32 + lane] = x1 * r;
}

// ---------------------------------------------------------------------------
// Gated delta rule recurrence.  One block per (seq b, head h).
// 256 threads: tid = v*4 + kh, each thread owns S[kh*16 .. kh*16+15, v].
// ---------------------------------------------------------------------------
__global__ __launch_bounds__(256) void recurrence_kernel(
    const float* __restrict__ qkv, const float* __restrict__ beta,
    const float* __restrict__ gate, const int* __restrict__ cu,
    float* __restrict__ O)
{
    const int b = blockIdx.x >> 4;
    const int h = blockIdx.x & 15;
    const int start = cu[b];
    const int end   = cu[b + 1];

    const int tid = threadIdx.x;
    const int v  = tid >> 2;
    const int kh = tid & 3;

    const int qoff = (h >> 1) * 64;            // repeated head mapping h -> h/2
    const int koff = KEY_DIM + (h >> 1) * 64;
    const int voff = 2 * KEY_DIM + h * 64;

    float S[16];
#pragma unroll
    for (int i = 0; i < 16; i++) S[i] = 0.f;

    __shared__ float sk[64];
    __shared__ float sq[64];

    for (int t = start; t < end; t++) {
        const float* __restrict__ row = qkv + (size_t)t * CONV_DIM;
        if (tid < 64)       sk[tid]      = row[koff + tid];
        else if (tid < 128) sq[tid - 64] = row[qoff + tid - 64];

        const float gexp = expf(gate[(size_t)t * HV + h]);
        const float bt   = beta[(size_t)t * HV + h];
        const float vt   = row[voff + v];
        __syncthreads();

        const float* __restrict__ skp = sk + kh * 16;
        const float* __restrict__ sqp = sq + kh * 16;

        float kv = 0.f;
#pragma unroll
        for (int i = 0; i < 16; i++) {
            S[i] *= gexp;
            kv = fmaf(skp[i], S[i], kv);
        }
        kv += __shfl_xor_sync(0xffffffffu, kv, 1);
        kv += __shfl_xor_sync(0xffffffffu, kv, 2);

        const float delta = bt * (vt - kv);

        float o = 0.f;
#pragma unroll
        for (int i = 0; i < 16; i++) {
            S[i] = fmaf(skp[i], delta, S[i]);
            o = fmaf(sqp[i], S[i], o);
        }
        o += __shfl_xor_sync(0xffffffffu, o, 1);
        o += __shfl_xor_sync(0xffffffffu, o, 2);

        if (kh == 0) O[(size_t)t * VAL_DIM + h * 64 + v] = o;
        __syncthreads();
    }
}

// ---------------------------------------------------------------------------
// Gated RMSNorm: on = o * rsqrt(mean(o^2) + eps) * norm_weight * silu(z)
// 16 warps per token, warp = head.
// ---------------------------------------------------------------------------
__global__ __launch_bounds__(512) void rmsnorm_kernel(
    const float* __restrict__ o, const float* __restrict__ z,
    const float* __restrict__ nw, float* __restrict__ on)
{
    const int t = blockIdx.x;
    const int w = threadIdx.x >> 5;
    const int lane = threadIdx.x & 31;
    const size_t base = (size_t)t * VAL_DIM + w * 64;

    float x0 = o[base + lane];
    float x1 = o[base + 32 + lane];
    float ss = x0 * x0 + x1 * x1;
#pragma unroll
    for (int off = 16; off; off >>= 1)
        ss += __shfl_xor_sync(0xffffffffu, ss, off);
    float r = rsqrtf(ss * (1.f / 64.f) + 1e-6f);

    float z0 = z[base + lane];
    float z1 = z[base + 32 + lane];
    float s0 = z0 / (1.f + expf(-z0));
    float s1 = z1 / (1.f + expf(-z1));

    on[base + lane]      = x0 * r * nw[lane]      * s0;
    on[base + 32 + lane] = x1 * r * nw[lane + 32] * s1;
}

// ---------------------------------------------------------------------------
extern "C" void kernel_launch(void* const* d_in, const int* in_sizes, int n_in,
                              void* d_out, int out_size)
{
    const float* hs     = (const float*)d_in[0];
    const float* W_qkv  = (const float*)d_in[1];
    const float* W_z    = (const float*)d_in[2];
    const float* W_b    = (const float*)d_in[3];
    const float* W_a    = (const float*)d_in[4];
    const float* conv_w = (const float*)d_in[5];
    const float* dt_b   = (const float*)d_in[6];
    const float* A_log  = (const float*)d_in[7];
    const float* norm_w = (const float*)d_in[8];
    const float* W_out  = (const float*)d_in[9];
    const int*   cu     = (const int*)d_in[10];

    const int total = in_sizes[0] / HIDDEN;       // 1536
    const int B     = in_sizes[10] - 1;           // 4

    float *mixed, *qkv, *zbuf, *betab, *gateb, *obuf, *onbuf;
    cudaGetSymbolAddress((void**)&mixed, g_mixed);
    cudaGetSymbolAddress((void**)&qkv,   g_qkv);
    cudaGetSymbolAddress((void**)&zbuf,  g_z);
    cudaGetSymbolAddress((void**)&betab, g_beta);
    cudaGetSymbolAddress((void**)&gateb, g_gate);
    cudaGetSymbolAddress((void**)&obuf,  g_o);
    cudaGetSymbolAddress((void**)&onbuf, g_on);

    // 1) big projections
    sgemm_tn<<<dim3(CONV_DIM / BN, total / BM), 256>>>(hs, W_qkv, mixed, total, CONV_DIM, HIDDEN);
    sgemm_tn<<<dim3(VAL_DIM  / BN, total / BM), 256>>>(hs, W_z,   zbuf,  total, VAL_DIM,  HIDDEN);

    // 2) b,a projections + beta/g
    ba_kernel<<<total, 256>>>(hs, W_b, W_a, dt_b, A_log, betab, gateb);

    // 3) causal conv + silu
    conv_silu_kernel<<<dim3(total, CONV_DIM / 256), 256>>>(mixed, conv_w, cu, B, qkv);

    // 4) q/k L2 normalization
    qknorm_kernel<<<total, 512>>>(qkv);

    // 5) gated delta rule recurrence
    recurrence_kernel<<<B * HV, 256>>>(qkv, betab, gateb, cu, obuf);

    // 6) gated RMSNorm
    rmsnorm_kernel<<<total, 512>>>(obuf, zbuf, norm_w, onbuf);

    // 7) output projection -> d_out
    sgemm_tn<<<dim3(HIDDEN / BN, total / BM), 256>>>(onbuf, W_out, (float*)d_out, total, HIDDEN, VAL_DIM);
}

// round 2
// speedup vs baseline: 1.2486x; 1.2486x over previous
#include <cuda_runtime.h>
#include <cuda_bf16.h>
#include <math.h>

// ---------------------------------------------------------------------------
// GatedDeltaNetVarlen — round 2: tensor-core GEMMs (bf16 2-term split, 3-pass)
// ---------------------------------------------------------------------------

#define TOTAL_MAX 1536
#define HIDDEN    1024
#define CONV_DIM  2048
#define KEY_DIM   512
#define VAL_DIM   1024
#define HK        8
#define HV        16
#define DK        64
#define DV        64
#define KSZ       4

typedef __nv_bfloat16 bf16;

__device__ float g_mixed[TOTAL_MAX * CONV_DIM];
__device__ float g_qkv  [TOTAL_MAX * CONV_DIM];
__device__ float g_z    [TOTAL_MAX * VAL_DIM];
__device__ float g_beta [TOTAL_MAX * HV];
__device__ float g_gate [TOTAL_MAX * HV];
__device__ float g_o    [TOTAL_MAX * VAL_DIM];

// bf16 split buffers
__device__ bf16 g_hs_h  [TOTAL_MAX * HIDDEN];
__device__ bf16 g_hs_l  [TOTAL_MAX * HIDDEN];
__device__ bf16 g_wqkv_h[CONV_DIM * HIDDEN];
__device__ bf16 g_wqkv_l[CONV_DIM * HIDDEN];
__device__ bf16 g_wz_h  [VAL_DIM * HIDDEN];
__device__ bf16 g_wz_l  [VAL_DIM * HIDDEN];
__device__ bf16 g_wout_h[HIDDEN * VAL_DIM];
__device__ bf16 g_wout_l[HIDDEN * VAL_DIM];
__device__ bf16 g_on_h  [TOTAL_MAX * VAL_DIM];
__device__ bf16 g_on_l  [TOTAL_MAX * VAL_DIM];

// ---------------------------------------------------------------------------
// Split fp32 -> (hi, lo) bf16
// ---------------------------------------------------------------------------
__global__ __launch_bounds__(256) void split_kernel(
    const float* __restrict__ x, bf16* __restrict__ h, bf16* __restrict__ l, int n)
{
    int i = blockIdx.x * blockDim.x + threadIdx.x;
    if (i < n) {
        float v = x[i];
        bf16 hh = __float2bfloat16(v);
        h[i] = hh;
        l[i] = __float2bfloat16(v - __bfloat162float(hh));
    }
}

// ---------------------------------------------------------------------------
// bf16 split GEMM:  C[M,N] = A[M,1024] @ B[N,1024]^T  computed as
//   Ah@Bh^T + Al@Bh^T + Ah@Bl^T  via mma.sync.m16n8k16
// BM=BN=128, BK=32, 256 threads (8 warps, 4x2), warp tile 32x64.
// K fixed at 1024.  M%128==0, N%128==0.
// ---------------------------------------------------------------------------
#define GK 1024
#define SSTR 40   // smem row stride (bf16 units), conflict-free for frag loads

__device__ __forceinline__ void mma16816(float* c, const unsigned* a, const unsigned* b)
{
    asm volatile(
        "mma.sync.aligned.m16n8k16.row.col.f32.bf16.bf16.f32 "
        "{%0,%1,%2,%3},{%4,%5,%6,%7},{%8,%9},{%0,%1,%2,%3};\n"
        : "+f"(c[0]), "+f"(c[1]), "+f"(c[2]), "+f"(c[3])
        : "r"(a[0]), "r"(a[1]), "r"(a[2]), "r"(a[3]), "r"(b[0]), "r"(b[1]));
}

__global__ __launch_bounds__(256) void gemm_bf16split(
    const bf16* __restrict__ Ah, const bf16* __restrict__ Al,
    const bf16* __restrict__ Bh, const bf16* __restrict__ Bl,
    float* __restrict__ C, int M, int N)
{
    __shared__ bf16 As[2][128][SSTR];
    __shared__ bf16 Bs[2][128][SSTR];

    const int tid  = threadIdx.x;
    const int lane = tid & 31;
    const int wid  = tid >> 5;
    const int wm   = wid & 3;     // warp row (0..3), 32 rows each
    const int wn   = wid >> 2;    // warp col (0..1), 64 cols each
    const int bm   = blockIdx.y * 128;
    const int bn   = blockIdx.x * 128;

    const int g  = lane >> 2;     // 0..7
    const int t4 = lane & 3;      // 0..3

    // global loader mapping
    const int lrow = tid >> 2;          // 0..63
    const int lcol = (tid & 3) * 8;     // bf16 units, 0/8/16/24

    const bf16* APs[3] = { Ah, Al, Ah };
    const bf16* BPs[3] = { Bh, Bh, Bl };

    float c[2][8][4];
#pragma unroll
    for (int mi = 0; mi < 2; mi++)
#pragma unroll
        for (int ni = 0; ni < 8; ni++)
#pragma unroll
            for (int r = 0; r < 4; r++) c[mi][ni][r] = 0.f;

    const int NIT = 3 * (GK / 32);   // 96

    // --- preload iteration 0 ---
    {
        const bf16* Ap = APs[0];
        const bf16* Bp = BPs[0];
        uint4 pa0 = *(const uint4*)(Ap + (size_t)(bm + lrow) * GK + lcol);
        uint4 pa1 = *(const uint4*)(Ap + (size_t)(bm + lrow + 64) * GK + lcol);
        uint4 pb0 = *(const uint4*)(Bp + (size_t)(bn + lrow) * GK + lcol);
        uint4 pb1 = *(const uint4*)(Bp + (size_t)(bn + lrow + 64) * GK + lcol);
        *(uint4*)&As[0][lrow][lcol]      = pa0;
        *(uint4*)&As[0][lrow + 64][lcol] = pa1;
        *(uint4*)&Bs[0][lrow][lcol]      = pb0;
        *(uint4*)&Bs[0][lrow + 64][lcol] = pb1;
    }
    __syncthreads();

    for (int it = 0; it < NIT; ++it) {
        const int cur = it & 1;
        const bool has_next = (it + 1 < NIT);

        uint4 pa0, pa1, pb0, pb1;
        if (has_next) {
            const int nit = it + 1;
            const int p  = nit >> 5;
            const int k0 = (nit & 31) * 32;
            const bf16* Ap = APs[p];
            const bf16* Bp = BPs[p];
            pa0 = *(const uint4*)(Ap + (size_t)(bm + lrow) * GK + k0 + lcol);
            pa1 = *(const uint4*)(Ap + (size_t)(bm + lrow + 64) * GK + k0 + lcol);
            pb0 = *(const uint4*)(Bp + (size_t)(bn + lrow) * GK + k0 + lcol);
            pb1 = *(const uint4*)(Bp + (size_t)(bn + lrow + 64) * GK + k0 + lcol);
        }

        // --- compute current buffer ---
#pragma unroll
        for (int kk = 0; kk < 32; kk += 16) {
            unsigned a[2][4], b[8][2];
#pragma unroll
            for (int mi = 0; mi < 2; mi++) {
                const bf16* Ab = &As[cur][wm * 32 + mi * 16 + g][kk + 2 * t4];
                a[mi][0] = *(const unsigned*)(Ab);
                a[mi][1] = *(const unsigned*)(Ab + 8 * SSTR);
                a[mi][2] = *(const unsigned*)(Ab + 8);
                a[mi][3] = *(const unsigned*)(Ab + 8 * SSTR + 8);
            }
#pragma unroll
            for (int ni = 0; ni < 8; ni++) {
                const bf16* Bb = &Bs[cur][wn * 64 + ni * 8 + g][kk + 2 * t4];
                b[ni][0] = *(const unsigned*)(Bb);
                b[ni][1] = *(const unsigned*)(Bb + 8);
            }
#pragma unroll
            for (int mi = 0; mi < 2; mi++)
#pragma unroll
                for (int ni = 0; ni < 8; ni++)
                    mma16816(c[mi][ni], a[mi], b[ni]);
        }

        if (has_next) {
            const int nxt = cur ^ 1;
            *(uint4*)&As[nxt][lrow][lcol]      = pa0;
            *(uint4*)&As[nxt][lrow + 64][lcol] = pa1;
            *(uint4*)&Bs[nxt][lrow][lcol]      = pb0;
            *(uint4*)&Bs[nxt][lrow + 64][lcol] = pb1;
            __syncthreads();
        }
    }

    // --- epilogue ---
#pragma unroll
    for (int mi = 0; mi < 2; mi++) {
        const int row0 = bm + wm * 32 + mi * 16 + g;
#pragma unroll
        for (int ni = 0; ni < 8; ni++) {
            const int col = bn + wn * 64 + ni * 8 + 2 * t4;
            *(float2*)(C + (size_t)row0 * N + col)       = make_float2(c[mi][ni][0], c[mi][ni][1]);
            *(float2*)(C + (size_t)(row0 + 8) * N + col) = make_float2(c[mi][ni][2], c[mi][ni][3]);
        }
    }
}

// ---------------------------------------------------------------------------
// b,a projections fused with beta = sigmoid(b), g = -exp(A_log)*softplus(a+dt)
// ---------------------------------------------------------------------------
__global__ __launch_bounds__(256) void ba_kernel(
    const float* __restrict__ hs,
    const float* __restrict__ Wb, const float* __restrict__ Wa,
    const float* __restrict__ dtb, const float* __restrict__ Alog,
    float* __restrict__ beta, float* __restrict__ gate)
{
    const int t = blockIdx.x;
    const int w = threadIdx.x >> 5;
    const int lane = threadIdx.x & 31;
    const int obase = w * 4;

    const float* __restrict__ x = hs + (size_t)t * HIDDEN;
    const float* Wp[4];
#pragma unroll
    for (int r = 0; r < 4; r++) {
        int o = obase + r;
        Wp[r] = (o < HV) ? (Wb + (size_t)o * HIDDEN) : (Wa + (size_t)(o - HV) * HIDDEN);
    }

    float acc[4] = {0.f, 0.f, 0.f, 0.f};
#pragma unroll 4
    for (int i = 0; i < HIDDEN / 32; i++) {
        float xv = x[i * 32 + lane];
#pragma unroll
        for (int r = 0; r < 4; r++)
            acc[r] = fmaf(xv, Wp[r][i * 32 + lane], acc[r]);
    }
#pragma unroll
    for (int r = 0; r < 4; r++)
#pragma unroll
        for (int off = 16; off; off >>= 1)
            acc[r] += __shfl_xor_sync(0xffffffffu, acc[r], off);

    if (lane == 0) {
#pragma unroll
        for (int r = 0; r < 4; r++) {
            int o = obase + r;
            if (o < HV) {
                beta[(size_t)t * HV + o] = 1.f / (1.f + expf(-acc[r]));
            } else {
                int h = o - HV;
                float xv = acc[r] + dtb[h];
                float sp = (xv > 20.f) ? xv : log1pf(expf(xv));
                gate[(size_t)t * HV + h] = -expf(Alog[h]) * sp;
            }
        }
    }
}

// ---------------------------------------------------------------------------
// Causal depthwise conv (ksz=4, per-sequence) + silu
// ---------------------------------------------------------------------------
__global__ __launch_bounds__(256) void conv_silu_kernel(
    const float* __restrict__ mixed, const float* __restrict__ cw,
    const int* __restrict__ cu, int B, float* __restrict__ out)
{
    const int t = blockIdx.x;
    const int c = blockIdx.y * blockDim.x + threadIdx.x;

    int start = 0;
    for (int i = 1; i < B; i++) { int s = cu[i]; if (t >= s) start = s; }

    const float w0 = cw[c * 4 + 0], w1 = cw[c * 4 + 1];
    const float w2 = cw[c * 4 + 2], w3 = cw[c * 4 + 3];

    float y = mixed[(size_t)t * CONV_DIM + c] * w3;
    if (t - 1 >= start) y = fmaf(mixed[(size_t)(t - 1) * CONV_DIM + c], w2, y);
    if (t - 2 >= start) y = fmaf(mixed[(size_t)(t - 2) * CONV_DIM + c], w1, y);
    if (t - 3 >= start) y = fmaf(mixed[(size_t)(t - 3) * CONV_DIM + c], w0, y);

    y = y / (1.f + expf(-y));
    out[(size_t)t * CONV_DIM + c] = y;
}

// ---------------------------------------------------------------------------
// Per-head L2 norm of q and k (q scaled by DK^-0.5)
// ---------------------------------------------------------------------------
__global__ __launch_bounds__(512) void qknorm_kernel(float* __restrict__ qkv)
{
    const int t = blockIdx.x;
    const int w = threadIdx.x >> 5;
    const int lane = threadIdx.x & 31;
    const size_t base = (size_t)t * CONV_DIM + w * 64;

    float x0 = qkv[base + lane];
    float x1 = qkv[base + 32 + lane];
    float ss = x0 * x0 + x1 * x1;
#pragma unroll
    for (int off = 16; off; off >>= 1)
        ss += __shfl_xor_sync(0xffffffffu, ss, off);
    float r = rsqrtf(ss + 1e-6f);
    if (w < 8) r *= 0.125f;
    qkv[base + lane]      = x0 * r;
    qkv[base + 32 + lane] = x1 * r;
}

// ---------------------------------------------------------------------------
// Gated delta rule recurrence.  One block per (seq b, head h).
// ---------------------------------------------------------------------------
__global__ __launch_bounds__(256) void recurrence_kernel(
    const float* __restrict__ qkv, const float* __restrict__ beta,
    const float* __restrict__ gate, const int* __restrict__ cu,
    float* __restrict__ O)
{
    const int b = blockIdx.x >> 4;
    const int h = blockIdx.x & 15;
    const int start = cu[b];
    const int end   = cu[b + 1];

    const int tid = threadIdx.x;
    const int v  = tid >> 2;
    const int kh = tid & 3;

    const int qoff = (h >> 1) * 64;
    const int koff = KEY_DIM + (h >> 1) * 64;
    const int voff = 2 * KEY_DIM + h * 64;

    float S[16];
#pragma unroll
    for (int i = 0; i < 16; i++) S[i] = 0.f;

    __shared__ float sk[64];
    __shared__ float sq[64];

    for (int t = start; t < end; t++) {
        const float* __restrict__ row = qkv + (size_t)t * CONV_DIM;
        if (tid < 64)       sk[tid]      = row[koff + tid];
        else if (tid < 128) sq[tid - 64] = row[qoff + tid - 64];

        const float gexp = expf(gate[(size_t)t * HV + h]);
        const float bt   = beta[(size_t)t * HV + h];
        const float vt   = row[voff + v];
        __syncthreads();

        const float* __restrict__ skp = sk + kh * 16;
        const float* __restrict__ sqp = sq + kh * 16;

        float kv = 0.f;
#pragma unroll
        for (int i = 0; i < 16; i++) {
            S[i] *= gexp;
            kv = fmaf(skp[i], S[i], kv);
        }
        kv += __shfl_xor_sync(0xffffffffu, kv, 1);
        kv += __shfl_xor_sync(0xffffffffu, kv, 2);

        const float delta = bt * (vt - kv);

        float o = 0.f;
#pragma unroll
        for (int i = 0; i < 16; i++) {
            S[i] = fmaf(skp[i], delta, S[i]);
            o = fmaf(sqp[i], S[i], o);
        }
        o += __shfl_xor_sync(0xffffffffu, o, 1);
        o += __shfl_xor_sync(0xffffffffu, o, 2);

        if (kh == 0) O[(size_t)t * VAL_DIM + h * 64 + v] = o;
        __syncthreads();
    }
}

// ---------------------------------------------------------------------------
// Gated RMSNorm fused with bf16 split of the result (feeds out-projection)
// ---------------------------------------------------------------------------
__global__ __launch_bounds__(512) void rmsnorm_split_kernel(
    const float* __restrict__ o, const float* __restrict__ z,
    const float* __restrict__ nw, bf16* __restrict__ onh, bf16* __restrict__ onl)
{
    const int t = blockIdx.x;
    const int w = threadIdx.x >> 5;
    const int lane = threadIdx.x & 31;
    const size_t base = (size_t)t * VAL_DIM + w * 64;

    float x0 = o[base + lane];
    float x1 = o[base + 32 + lane];
    float ss = x0 * x0 + x1 * x1;
#pragma unroll
    for (int off = 16; off; off >>= 1)
        ss += __shfl_xor_sync(0xffffffffu, ss, off);
    float r = rsqrtf(ss * (1.f / 64.f) + 1e-6f);

    float z0 = z[base + lane];
    float z1 = z[base + 32 + lane];
    float s0 = z0 / (1.f + expf(-z0));
    float s1 = z1 / (1.f + expf(-z1));

    float v0 = x0 * r * nw[lane]      * s0;
    float v1 = x1 * r * nw[lane + 32] * s1;

    bf16 h0 = __float2bfloat16(v0);
    bf16 h1 = __float2bfloat16(v1);
    onh[base + lane]      = h0;
    onh[base + 32 + lane] = h1;
    onl[base + lane]      = __float2bfloat16(v0 - __bfloat162float(h0));
    onl[base + 32 + lane] = __float2bfloat16(v1 - __bfloat162float(h1));
}

// ---------------------------------------------------------------------------
extern "C" void kernel_launch(void* const* d_in, const int* in_sizes, int n_in,
                              void* d_out, int out_size)
{
    const float* hs     = (const float*)d_in[0];
    const float* W_qkv  = (const float*)d_in[1];
    const float* W_z    = (const float*)d_in[2];
    const float* W_b    = (const float*)d_in[3];
    const float* W_a    = (const float*)d_in[4];
    const float* conv_w = (const float*)d_in[5];
    const float* dt_b   = (const float*)d_in[6];
    const float* A_log  = (const float*)d_in[7];
    const float* norm_w = (const float*)d_in[8];
    const float* W_out  = (const float*)d_in[9];
    const int*   cu     = (const int*)d_in[10];

    const int total = in_sizes[0] / HIDDEN;       // 1536
    const int B     = in_sizes[10] - 1;           // 4

    float *mixed, *qkv, *zbuf, *betab, *gateb, *obuf;
    bf16 *hs_h, *hs_l, *wqkv_h, *wqkv_l, *wz_h, *wz_l, *wout_h, *wout_l, *on_h, *on_l;
    cudaGetSymbolAddress((void**)&mixed,  g_mixed);
    cudaGetSymbolAddress((void**)&qkv,    g_qkv);
    cudaGetSymbolAddress((void**)&zbuf,   g_z);
    cudaGetSymbolAddress((void**)&betab,  g_beta);
    cudaGetSymbolAddress((void**)&gateb,  g_gate);
    cudaGetSymbolAddress((void**)&obuf,   g_o);
    cudaGetSymbolAddress((void**)&hs_h,   g_hs_h);
    cudaGetSymbolAddress((void**)&hs_l,   g_hs_l);
    cudaGetSymbolAddress((void**)&wqkv_h, g_wqkv_h);
    cudaGetSymbolAddress((void**)&wqkv_l, g_wqkv_l);
    cudaGetSymbolAddress((void**)&wz_h,   g_wz_h);
    cudaGetSymbolAddress((void**)&wz_l,   g_wz_l);
    cudaGetSymbolAddress((void**)&wout_h, g_wout_h);
    cudaGetSymbolAddress((void**)&wout_l, g_wout_l);
    cudaGetSymbolAddress((void**)&on_h,   g_on_h);
    cudaGetSymbolAddress((void**)&on_l,   g_on_l);

    // 0) bf16 splits
    split_kernel<<<(total * HIDDEN + 255) / 256, 256>>>(hs, hs_h, hs_l, total * HIDDEN);
    split_kernel<<<(CONV_DIM * HIDDEN + 255) / 256, 256>>>(W_qkv, wqkv_h, wqkv_l, CONV_DIM * HIDDEN);
    split_kernel<<<(VAL_DIM * HIDDEN + 255) / 256, 256>>>(W_z, wz_h, wz_l, VAL_DIM * HIDDEN);
    split_kernel<<<(HIDDEN * VAL_DIM + 255) / 256, 256>>>(W_out, wout_h, wout_l, HIDDEN * VAL_DIM);

    // 1) big projections on tensor cores
    gemm_bf16split<<<dim3(CONV_DIM / 128, total / 128), 256>>>(hs_h, hs_l, wqkv_h, wqkv_l, mixed, total, CONV_DIM);
    gemm_bf16split<<<dim3(VAL_DIM / 128, total / 128), 256>>>(hs_h, hs_l, wz_h, wz_l, zbuf, total, VAL_DIM);

    // 2) b,a projections + beta/g
    ba_kernel<<<total, 256>>>(hs, W_b, W_a, dt_b, A_log, betab, gateb);

    // 3) causal conv + silu
    conv_silu_kernel<<<dim3(total, CONV_DIM / 256), 256>>>(mixed, conv_w, cu, B, qkv);

    // 4) q/k L2 normalization
    qknorm_kernel<<<total, 512>>>(qkv);

    // 5) gated delta rule recurrence
    recurrence_kernel<<<B * HV, 256>>>(qkv, betab, gateb, cu, obuf);

    // 6) gated RMSNorm + split
    rmsnorm_split_kernel<<<total, 512>>>(obuf, zbuf, norm_w, on_h, on_l);

    // 7) output projection -> d_out
    gemm_bf16split<<<dim3(HIDDEN / 128, total / 128), 256>>>(on_h, on_l, wout_h, wout_l, (float*)d_out, total, HIDDEN);
}

// round 3
// speedup vs baseline: 1.4790x; 1.1846x over previous
#include <cuda_runtime.h>
#include <cuda_bf16.h>
#include <math.h>

// ---------------------------------------------------------------------------
// GatedDeltaNetVarlen — round 3:
//   * ldmatrix-based bf16-split GEMMs (LDS-bound -> tensor-bound)
//   * fused hs projection (W_qkv || W_z in one launch, 1 wave)
//   * restructured recurrence: parallel dots, 1 barrier/step, prefetch
//   * fused conv + qk-norm, vectorized splits
// ---------------------------------------------------------------------------

#define TOTAL_MAX 1536
#define HIDDEN    1024
#define CONV_DIM  2048
#define KEY_DIM   512
#define VAL_DIM   1024
#define HV        16
#define GK        1024
#define SSTR      40     // smem row stride (bf16), conflict-free for LDSM

typedef __nv_bfloat16 bf16;

__device__ float g_mixed[TOTAL_MAX * CONV_DIM];
__device__ float g_qkv  [TOTAL_MAX * CONV_DIM];
__device__ float g_z    [TOTAL_MAX * VAL_DIM];
__device__ float g_beta [TOTAL_MAX * HV];
__device__ float g_gate [TOTAL_MAX * HV];
__device__ float g_o    [TOTAL_MAX * VAL_DIM];

__device__ bf16 g_hs_h  [TOTAL_MAX * HIDDEN];
__device__ bf16 g_hs_l  [TOTAL_MAX * HIDDEN];
__device__ bf16 g_wqkv_h[CONV_DIM * HIDDEN];
__device__ bf16 g_wqkv_l[CONV_DIM * HIDDEN];
__device__ bf16 g_wz_h  [VAL_DIM * HIDDEN];
__device__ bf16 g_wz_l  [VAL_DIM * HIDDEN];
__device__ bf16 g_wout_h[HIDDEN * VAL_DIM];
__device__ bf16 g_wout_l[HIDDEN * VAL_DIM];
__device__ bf16 g_on_h  [TOTAL_MAX * VAL_DIM];
__device__ bf16 g_on_l  [TOTAL_MAX * VAL_DIM];

// ---------------------------------------------------------------------------
// Vectorized fp32 -> (hi,lo) bf16 split
// ---------------------------------------------------------------------------
__global__ __launch_bounds__(256) void split4_kernel(
    const float4* __restrict__ x, uint2* __restrict__ h, uint2* __restrict__ l, int n4)
{
    int i = blockIdx.x * blockDim.x + threadIdx.x;
    if (i >= n4) return;
    float4 v = x[i];
    bf16 h0 = __float2bfloat16(v.x), h1 = __float2bfloat16(v.y);
    bf16 h2 = __float2bfloat16(v.z), h3 = __float2bfloat16(v.w);
    bf16 l0 = __float2bfloat16(v.x - __bfloat162float(h0));
    bf16 l1 = __float2bfloat16(v.y - __bfloat162float(h1));
    bf16 l2 = __float2bfloat16(v.z - __bfloat162float(h2));
    bf16 l3 = __float2bfloat16(v.w - __bfloat162float(h3));
    uint2 hv, lv;
    hv.x = ((unsigned)__bfloat16_as_ushort(h1) << 16) | __bfloat16_as_ushort(h0);
    hv.y = ((unsigned)__bfloat16_as_ushort(h3) << 16) | __bfloat16_as_ushort(h2);
    lv.x = ((unsigned)__bfloat16_as_ushort(l1) << 16) | __bfloat16_as_ushort(l0);
    lv.y = ((unsigned)__bfloat16_as_ushort(l3) << 16) | __bfloat16_as_ushort(l2);
    h[i] = hv;
    l[i] = lv;
}

// ---------------------------------------------------------------------------
// ldmatrix helpers
// ---------------------------------------------------------------------------
__device__ __forceinline__ void ldsm_x4(unsigned& r0, unsigned& r1, unsigned& r2, unsigned& r3,
                                        const bf16* p)
{
    unsigned addr = (unsigned)__cvta_generic_to_shared(p);
    asm volatile("ldmatrix.sync.aligned.m8n8.x4.shared.b16 {%0,%1,%2,%3}, [%4];"
                 : "=r"(r0), "=r"(r1), "=r"(r2), "=r"(r3) : "r"(addr));
}

__device__ __forceinline__ void mma16816(float* c, const unsigned* a, const unsigned* b)
{
    asm volatile(
        "mma.sync.aligned.m16n8k16.row.col.f32.bf16.bf16.f32 "
        "{%0,%1,%2,%3},{%4,%5,%6,%7},{%8,%9},{%0,%1,%2,%3};\n"
        : "+f"(c[0]), "+f"(c[1]), "+f"(c[2]), "+f"(c[3])
        : "r"(a[0]), "r"(a[1]), "r"(a[2]), "r"(a[3]), "r"(b[0]), "r"(b[1]));
}

// ---------------------------------------------------------------------------
// bf16 split GEMM with dual output ranges:
//   cols [0, N1)        : C1 = A @ B1^T
//   cols [N1, N1+N2)    : C2 = A @ B2^T
// A: [M,1024] split (Ah, Al); B*: [N*,1024] split.  3 passes: hh, lh, hl.
// BM=BN=128, BK=32, 256 threads (8 warps 4x2), warp tile 32x64, LDSM + mma.
// ---------------------------------------------------------------------------
__global__ __launch_bounds__(256) void gemm_bf16split_dual(
    const bf16* __restrict__ Ah, const bf16* __restrict__ Al,
    const bf16* __restrict__ B1h, const bf16* __restrict__ B1l,
    const bf16* __restrict__ B2h, const bf16* __restrict__ B2l,
    float* __restrict__ C1, float* __restrict__ C2, int N1, int N2)
{
    __shared__ bf16 As[2][128][SSTR];
    __shared__ bf16 Bs[2][128][SSTR];

    const int tid  = threadIdx.x;
    const int lane = tid & 31;
    const int wid  = tid >> 5;
    const int wm   = wid & 3;
    const int wn   = wid >> 2;
    const int bm   = blockIdx.y * 128;
    const int bnG  = blockIdx.x * 128;

    const bf16* Bh; const bf16* Bl; float* C; int bn, ldc;
    if (bnG < N1) { Bh = B1h; Bl = B1l; C = C1; bn = bnG; ldc = N1; }
    else          { Bh = B2h; Bl = B2l; C = C2; bn = bnG - N1; ldc = N2; }

    const int lrow = tid >> 2;
    const int lcol = (tid & 3) * 8;

    const bf16* APs[3] = { Ah, Al, Ah };
    const bf16* BPs[3] = { Bh, Bh, Bl };

    float c[2][8][4];
#pragma unroll
    for (int mi = 0; mi < 2; mi++)
#pragma unroll
        for (int ni = 0; ni < 8; ni++)
#pragma unroll
            for (int r = 0; r < 4; r++) c[mi][ni][r] = 0.f;

    const int NIT = 3 * (GK / 32);

    {
        uint4 pa0 = *(const uint4*)(APs[0] + (size_t)(bm + lrow) * GK + lcol);
        uint4 pa1 = *(const uint4*)(APs[0] + (size_t)(bm + lrow + 64) * GK + lcol);
        uint4 pb0 = *(const uint4*)(BPs[0] + (size_t)(bn + lrow) * GK + lcol);
        uint4 pb1 = *(const uint4*)(BPs[0] + (size_t)(bn + lrow + 64) * GK + lcol);
        *(uint4*)&As[0][lrow][lcol]      = pa0;
        *(uint4*)&As[0][lrow + 64][lcol] = pa1;
        *(uint4*)&Bs[0][lrow][lcol]      = pb0;
        *(uint4*)&Bs[0][lrow + 64][lcol] = pb1;
    }
    __syncthreads();

    const int lrow16 = lane & 15;
    const int lhalf  = lane >> 4;
    const int l8     = lane & 7;
    const int grp    = lane >> 3;

    for (int it = 0; it < NIT; ++it) {
        const int cur = it & 1;
        const bool has_next = (it + 1 < NIT);

        uint4 pa0, pa1, pb0, pb1;
        if (has_next) {
            const int nit = it + 1;
            const int p  = nit >> 5;
            const int k0 = (nit & 31) * 32;
            pa0 = *(const uint4*)(APs[p] + (size_t)(bm + lrow) * GK + k0 + lcol);
            pa1 = *(const uint4*)(APs[p] + (size_t)(bm + lrow + 64) * GK + k0 + lcol);
            pb0 = *(const uint4*)(BPs[p] + (size_t)(bn + lrow) * GK + k0 + lcol);
            pb1 = *(const uint4*)(BPs[p] + (size_t)(bn + lrow + 64) * GK + k0 + lcol);
        }

#pragma unroll
        for (int kk = 0; kk < 32; kk += 16) {
            unsigned a[2][4];
#pragma unroll
            for (int mi = 0; mi < 2; mi++)
                ldsm_x4(a[mi][0], a[mi][1], a[mi][2], a[mi][3],
                        &As[cur][wm * 32 + mi * 16 + lrow16][kk + 8 * lhalf]);
            unsigned b[8][2];
#pragma unroll
            for (int nj = 0; nj < 4; nj++)
                ldsm_x4(b[2 * nj][0], b[2 * nj][1], b[2 * nj + 1][0], b[2 * nj + 1][1],
                        &Bs[cur][wn * 64 + nj * 16 + (grp >> 1) * 8 + l8][kk + 8 * (grp & 1)]);
#pragma unroll
            for (int mi = 0; mi < 2; mi++)
#pragma unroll
                for (int ni = 0; ni < 8; ni++)
                    mma16816(c[mi][ni], a[mi], b[ni]);
        }

        if (has_next) {
            const int nxt = cur ^ 1;
            *(uint4*)&As[nxt][lrow][lcol]      = pa0;
            *(uint4*)&As[nxt][lrow + 64][lcol] = pa1;
            *(uint4*)&Bs[nxt][lrow][lcol]      = pb0;
            *(uint4*)&Bs[nxt][lrow + 64][lcol] = pb1;
            __syncthreads();
        }
    }

    const int g  = lane >> 2;
    const int t4 = lane & 3;
#pragma unroll
    for (int mi = 0; mi < 2; mi++) {
        const int row0 = bm + wm * 32 + mi * 16 + g;
#pragma unroll
        for (int ni = 0; ni < 8; ni++) {
            const int col = bn + wn * 64 + ni * 8 + 2 * t4;
            *(float2*)(C + (size_t)row0 * ldc + col)       = make_float2(c[mi][ni][0], c[mi][ni][1]);
            *(float2*)(C + (size_t)(row0 + 8) * ldc + col) = make_float2(c[mi][ni][2], c[mi][ni][3]);
        }
    }
}

// ---------------------------------------------------------------------------
// b,a projections fused with beta / gate computation
// ---------------------------------------------------------------------------
__global__ __launch_bounds__(256) void ba_kernel(
    const float* __restrict__ hs,
    const float* __restrict__ Wb, const float* __restrict__ Wa,
    const float* __restrict__ dtb, const float* __restrict__ Alog,
    float* __restrict__ beta, float* __restrict__ gate)
{
    const int t = blockIdx.x;
    const int w = threadIdx.x >> 5;
    const int lane = threadIdx.x & 31;
    const int obase = w * 4;

    const float* __restrict__ x = hs + (size_t)t * HIDDEN;
    const float* Wp[4];
#pragma unroll
    for (int r = 0; r < 4; r++) {
        int o = obase + r;
        Wp[r] = (o < HV) ? (Wb + (size_t)o * HIDDEN) : (Wa + (size_t)(o - HV) * HIDDEN);
    }

    float acc[4] = {0.f, 0.f, 0.f, 0.f};
#pragma unroll 4
    for (int i = 0; i < HIDDEN / 32; i++) {
        float xv = x[i * 32 + lane];
#pragma unroll
        for (int r = 0; r < 4; r++)
            acc[r] = fmaf(xv, Wp[r][i * 32 + lane], acc[r]);
    }
#pragma unroll
    for (int r = 0; r < 4; r++)
#pragma unroll
        for (int off = 16; off; off >>= 1)
            acc[r] += __shfl_xor_sync(0xffffffffu, acc[r], off);

    if (lane == 0) {
#pragma unroll
        for (int r = 0; r < 4; r++) {
            int o = obase + r;
            if (o < HV) {
                beta[(size_t)t * HV + o] = 1.f / (1.f + expf(-acc[r]));
            } else {
                int h = o - HV;
                float xv = acc[r] + dtb[h];
                float sp = (xv > 20.f) ? xv : log1pf(expf(xv));
                gate[(size_t)t * HV + h] = -expf(Alog[h]) * sp;
            }
        }
    }
}

// ---------------------------------------------------------------------------
// Fused causal depthwise conv(4) + silu + per-head q/k L2 norm.
// One block per token, 256 threads, 8 channels per thread.
// ---------------------------------------------------------------------------
__global__ __launch_bounds__(256) void conv_norm_kernel(
    const float* __restrict__ mixed, const float* __restrict__ cw,
    const int* __restrict__ cu, int B, float* __restrict__ out)
{
    const int t = blockIdx.x;
    const int tid = threadIdx.x;
    const int c0 = tid * 8;

    int start = 0;
    for (int i = 1; i < B; i++) { int s = cu[i]; if (t >= s) start = s; }

    float y[8];
#pragma unroll
    for (int j = 0; j < 8; j++) {
        const int c = c0 + j;
        const float4 w4 = *(const float4*)(cw + c * 4);
        float acc = mixed[(size_t)t * CONV_DIM + c] * w4.w;
        if (t - 1 >= start) acc = fmaf(mixed[(size_t)(t - 1) * CONV_DIM + c], w4.z, acc);
        if (t - 2 >= start) acc = fmaf(mixed[(size_t)(t - 2) * CONV_DIM + c], w4.y, acc);
        if (t - 3 >= start) acc = fmaf(mixed[(size_t)(t - 3) * CONV_DIM + c], w4.x, acc);
        y[j] = acc / (1.f + expf(-acc));
    }

    if (c0 < 2 * KEY_DIM) {  // q/k channels: L2 norm per 64-channel head (8 threads)
        float ss = 0.f;
#pragma unroll
        for (int j = 0; j < 8; j++) ss = fmaf(y[j], y[j], ss);
        ss += __shfl_xor_sync(0xffffffffu, ss, 1);
        ss += __shfl_xor_sync(0xffffffffu, ss, 2);
        ss += __shfl_xor_sync(0xffffffffu, ss, 4);
        float r = rsqrtf(ss + 1e-6f);
        if (c0 < KEY_DIM) r *= 0.125f;   // q also scaled by DK^-0.5
#pragma unroll
        for (int j = 0; j < 8; j++) y[j] *= r;
    }

    float4* dst = (float4*)(out + (size_t)t * CONV_DIM + c0);
    dst[0] = make_float4(y[0], y[1], y[2], y[3]);
    dst[1] = make_float4(y[4], y[5], y[6], y[7]);
}

// ---------------------------------------------------------------------------
// Gated delta rule recurrence, restructured:
//   dk = k.S_old, dq = q.S_old, qk = q.k  (all in parallel)
//   kv = g*dk ; delta = beta*(v - kv) ; S = g*S + k*delta ; o = g*dq + qk*delta
// One block per (seq,head), 256 threads (v = tid>>2, kh = tid&3, 16 k each).
// Double-buffered smem (1 barrier/step) + register prefetch of step t+1.
// ---------------------------------------------------------------------------
__global__ __launch_bounds__(256) void recurrence_kernel(
    const float* __restrict__ qkv, const float* __restrict__ beta,
    const float* __restrict__ gate, const int* __restrict__ cu,
    float* __restrict__ O)
{
    const int b = blockIdx.x >> 4;
    const int h = blockIdx.x & 15;
    const int start = cu[b];
    const int end   = cu[b + 1];

    const int tid = threadIdx.x;
    const int v  = tid >> 2;
    const int kh = tid & 3;

    const int qoff = (h >> 1) * 64;
    const int koff = KEY_DIM + (h >> 1) * 64;
    const int voff = 2 * KEY_DIM + h * 64;

    float S[16];
#pragma unroll
    for (int i = 0; i < 16; i++) S[i] = 0.f;

    __shared__ float sk[2][64];
    __shared__ float sq[2][64];

    float rk = 0.f, rq = 0.f, vt = 0.f, gexp = 0.f, bt = 0.f;
    if (start < end) {
        const float* __restrict__ row = qkv + (size_t)start * CONV_DIM;
        if (tid < 64)       rk = row[koff + tid];
        else if (tid < 128) rq = row[qoff + tid - 64];
        gexp = expf(gate[(size_t)start * HV + h]);
        bt   = beta[(size_t)start * HV + h];
        vt   = row[voff + v];
    }

    for (int t = start; t < end; t++) {
        const int buf = t & 1;
        if (tid < 64)       sk[buf][tid]      = rk;
        else if (tid < 128) sq[buf][tid - 64] = rq;
        __syncthreads();

        const float cg = gexp, cb = bt, cv = vt;

        // prefetch step t+1
        if (t + 1 < end) {
            const float* __restrict__ nrow = qkv + (size_t)(t + 1) * CONV_DIM;
            if (tid < 64)       rk = nrow[koff + tid];
            else if (tid < 128) rq = nrow[qoff + tid - 64];
            gexp = expf(gate[(size_t)(t + 1) * HV + h]);
            bt   = beta[(size_t)(t + 1) * HV + h];
            vt   = nrow[voff + v];
        }

        float kf[16], qf[16];
        const float4* k4 = (const float4*)(sk[buf] + kh * 16);
        const float4* q4 = (const float4*)(sq[buf] + kh * 16);
#pragma unroll
        for (int j = 0; j < 4; j++) {
            float4 kv4 = k4[j]; float4 qv4 = q4[j];
            kf[4*j+0]=kv4.x; kf[4*j+1]=kv4.y; kf[4*j+2]=kv4.z; kf[4*j+3]=kv4.w;
            qf[4*j+0]=qv4.x; qf[4*j+1]=qv4.y; qf[4*j+2]=qv4.z; qf[4*j+3]=qv4.w;
        }

        // parallel dots with 4-way ILP
        float dk0=0,dk1=0,dk2=0,dk3=0, dq0=0,dq1=0,dq2=0,dq3=0, qk0=0,qk1=0,qk2=0,qk3=0;
#pragma unroll
        for (int j = 0; j < 4; j++) {
            dk0 = fmaf(kf[4*j+0], S[4*j+0], dk0);
            dk1 = fmaf(kf[4*j+1], S[4*j+1], dk1);
            dk2 = fmaf(kf[4*j+2], S[4*j+2], dk2);
            dk3 = fmaf(kf[4*j+3], S[4*j+3], dk3);
            dq0 = fmaf(qf[4*j+0], S[4*j+0], dq0);
            dq1 = fmaf(qf[4*j+1], S[4*j+1], dq1);
            dq2 = fmaf(qf[4*j+2], S[4*j+2], dq2);
            dq3 = fmaf(qf[4*j+3], S[4*j+3], dq3);
            qk0 = fmaf(qf[4*j+0], kf[4*j+0], qk0);
            qk1 = fmaf(qf[4*j+1], kf[4*j+1], qk1);
            qk2 = fmaf(qf[4*j+2], kf[4*j+2], qk2);
            qk3 = fmaf(qf[4*j+3], kf[4*j+3], qk3);
        }
        float dk = (dk0 + dk1) + (dk2 + dk3);
        float dq = (dq0 + dq1) + (dq2 + dq3);
        float qk = (qk0 + qk1) + (qk2 + qk3);

        dk += __shfl_xor_sync(0xffffffffu, dk, 1);
        dq += __shfl_xor_sync(0xffffffffu, dq, 1);
        qk += __shfl_xor_sync(0xffffffffu, qk, 1);
        dk += __shfl_xor_sync(0xffffffffu, dk, 2);
        dq += __shfl_xor_sync(0xffffffffu, dq, 2);
        qk += __shfl_xor_sync(0xffffffffu, qk, 2);

        const float kv    = cg * dk;
        const float delta = cb * (cv - kv);

#pragma unroll
        for (int i = 0; i < 16; i++)
            S[i] = fmaf(kf[i], delta, cg * S[i]);

        if (kh == 0) {
            const float o = fmaf(qk, delta, cg * dq);
            O[(size_t)t * VAL_DIM + h * 64 + v] = o;
        }
    }
}

// ---------------------------------------------------------------------------
// Gated RMSNorm fused with bf16 split (feeds out-projection)
// ---------------------------------------------------------------------------
__global__ __launch_bounds__(512) void rmsnorm_split_kernel(
    const float* __restrict__ o, const float* __restrict__ z,
    const float* __restrict__ nw, bf16* __restrict__ onh, bf16* __restrict__ onl)
{
    const int t = blockIdx.x;
    const int w = threadIdx.x >> 5;
    const int lane = threadIdx.x & 31;
    const size_t base = (size_t)t * VAL_DIM + w * 64;

    float x0 = o[base + lane];
    float x1 = o[base + 32 + lane];
    float ss = x0 * x0 + x1 * x1;
#pragma unroll
    for (int off = 16; off; off >>= 1)
        ss += __shfl_xor_sync(0xffffffffu, ss, off);
    float r = rsqrtf(ss * (1.f / 64.f) + 1e-6f);

    float z0 = z[base + lane];
    float z1 = z[base + 32 + lane];
    float s0 = z0 / (1.f + expf(-z0));
    float s1 = z1 / (1.f + expf(-z1));

    float v0 = x0 * r * nw[lane]      * s0;
    float v1 = x1 * r * nw[lane + 32] * s1;

    bf16 h0 = __float2bfloat16(v0);
    bf16 h1 = __float2bfloat16(v1);
    onh[base + lane]      = h0;
    onh[base + 32 + lane] = h1;
    onl[base + lane]      = __float2bfloat16(v0 - __bfloat162float(h0));
    onl[base + 32 + lane] = __float2bfloat16(v1 - __bfloat162float(h1));
}

// ---------------------------------------------------------------------------
extern "C" void kernel_launch(void* const* d_in, const int* in_sizes, int n_in,
                              void* d_out, int out_size)
{
    const float* hs     = (const float*)d_in[0];
    const float* W_qkv  = (const float*)d_in[1];
    const float* W_z    = (const float*)d_in[2];
    const float* W_b    = (const float*)d_in[3];
    const float* W_a    = (const float*)d_in[4];
    const float* conv_w = (const float*)d_in[5];
    const float* dt_b   = (const float*)d_in[6];
    const float* A_log  = (const float*)d_in[7];
    const float* norm_w = (const float*)d_in[8];
    const float* W_out  = (const float*)d_in[9];
    const int*   cu     = (const int*)d_in[10];

    const int total = in_sizes[0] / HIDDEN;       // 1536
    const int B     = in_sizes[10] - 1;           // 4

    float *mixed, *qkv, *zbuf, *betab, *gateb, *obuf;
    bf16 *hs_h, *hs_l, *wqkv_h, *wqkv_l, *wz_h, *wz_l, *wout_h, *wout_l, *on_h, *on_l;
    cudaGetSymbolAddress((void**)&mixed,  g_mixed);
    cudaGetSymbolAddress((void**)&qkv,    g_qkv);
    cudaGetSymbolAddress((void**)&zbuf,   g_z);
    cudaGetSymbolAddress((void**)&betab,  g_beta);
    cudaGetSymbolAddress((void**)&gateb,  g_gate);
    cudaGetSymbolAddress((void**)&obuf,   g_o);
    cudaGetSymbolAddress((void**)&hs_h,   g_hs_h);
    cudaGetSymbolAddress((void**)&hs_l,   g_hs_l);
    cudaGetSymbolAddress((void**)&wqkv_h, g_wqkv_h);
    cudaGetSymbolAddress((void**)&wqkv_l, g_wqkv_l);
    cudaGetSymbolAddress((void**)&wz_h,   g_wz_h);
    cudaGetSymbolAddress((void**)&wz_l,   g_wz_l);
    cudaGetSymbolAddress((void**)&wout_h, g_wout_h);
    cudaGetSymbolAddress((void**)&wout_l, g_wout_l);
    cudaGetSymbolAddress((void**)&on_h,   g_on_h);
    cudaGetSymbolAddress((void**)&on_l,   g_on_l);

    // 0-2) splits (hs, W_qkv, W_z)
    split4_kernel<<<(total * HIDDEN / 4 + 255) / 256, 256>>>(
        (const float4*)hs, (uint2*)hs_h, (uint2*)hs_l, total * HIDDEN / 4);
    split4_kernel<<<(CONV_DIM * HIDDEN / 4 + 255) / 256, 256>>>(
        (const float4*)W_qkv, (uint2*)wqkv_h, (uint2*)wqkv_l, CONV_DIM * HIDDEN / 4);
    split4_kernel<<<(VAL_DIM * HIDDEN / 4 + 255) / 256, 256>>>(
        (const float4*)W_z, (uint2*)wz_h, (uint2*)wz_l, VAL_DIM * HIDDEN / 4);

    // 3) fused hs projections (W_qkv || W_z) — launch index 3 = ncu capture slot
    gemm_bf16split_dual<<<dim3((CONV_DIM + VAL_DIM) / 128, total / 128), 256>>>(
        hs_h, hs_l, wqkv_h, wqkv_l, wz_h, wz_l, mixed, zbuf, CONV_DIM, VAL_DIM);

    // 4) W_out split
    split4_kernel<<<(HIDDEN * VAL_DIM / 4 + 255) / 256, 256>>>(
        (const float4*)W_out, (uint2*)wout_h, (uint2*)wout_l, HIDDEN * VAL_DIM / 4);

    // 5) b,a projections + beta/gate
    ba_kernel<<<total, 256>>>(hs, W_b, W_a, dt_b, A_log, betab, gateb);

    // 6) fused causal conv + silu + qk norm
    conv_norm_kernel<<<total, 256>>>(mixed, conv_w, cu, B, qkv);

    // 7) gated delta rule recurrence
    recurrence_kernel<<<B * HV, 256>>>(qkv, betab, gateb, cu, obuf);

    // 8) gated RMSNorm + split
    rmsnorm_split_kernel<<<total, 512>>>(obuf, zbuf, norm_w, on_h, on_l);

    // 9) output projection -> d_out
    gemm_bf16split_dual<<<dim3(HIDDEN / 128, total / 128), 256>>>(
        on_h, on_l, wout_h, wout_l, wout_h, wout_l, (float*)d_out, (float*)d_out,
        HIDDEN, 0);
}